// round 15
// baseline (speedup 1.0000x reference)
#include <cuda_runtime.h>
#include <cuda_fp16.h>
#include <stdint.h>

#define BB   512
#define TW   512
#define TCC  512
#define INP  16
#define HID  64
#define FD   8
#define SPB  4
#define NT   1024
#define HPAD 68
#define GPAD 260
#define U0S  88    // uf0 stride in halfs (K=80 + pad)
#define U1S  136   // uf1 stride in halfs (K=128 + pad)

__device__ __forceinline__ float tanha(float x) {
    float r; asm("tanh.approx.f32 %0, %1;" : "=f"(r) : "f"(x)); return r;
}
__device__ __forceinline__ float sigf(float x) {
    return fmaf(tanha(0.5f * x), 0.5f, 0.5f);
}
__device__ __forceinline__ uint32_t h2(float a, float b) {
    __half2 h = __floats2half2_rn(a, b);
    return *reinterpret_cast<uint32_t*>(&h);
}
__device__ __forceinline__ void mma16816(
    float* d, const uint32_t* a, uint32_t b0, uint32_t b1)
{
    asm("mma.sync.aligned.m16n8k16.row.col.f32.f16.f16.f32 "
        "{%0,%1,%2,%3},{%4,%5,%6,%7},{%8,%9},{%0,%1,%2,%3};"
        : "+f"(d[0]), "+f"(d[1]), "+f"(d[2]), "+f"(d[3])
        : "r"(a[0]), "r"(a[1]), "r"(a[2]), "r"(a[3]), "r"(b0), "r"(b1));
}

__global__ __launch_bounds__(NT, 1) void lstm_ar_kernel(
    const float* __restrict__ x,     const int* __restrict__ lenx_g,
    const float* __restrict__ ctx,   const int* __restrict__ lctx_g,
    const float* __restrict__ Wih0,  const float* __restrict__ Whh0,
    const float* __restrict__ bih0,  const float* __restrict__ bhh0,
    const float* __restrict__ Wih1,  const float* __restrict__ Whh1,
    const float* __restrict__ bih1,  const float* __restrict__ bhh1,
    const float* __restrict__ Wd,    const float* __restrict__ bd,
    float* __restrict__ out)
{
    __shared__ __align__(16) __half uf0[8][U0S];   // [x(16)|h0(64)] per sample
    __shared__ __align__(16) __half uf1[8][U1S];   // [h0|h1] per sample
    __shared__ __align__(16) float g0sh[SPB][GPAD];
    __shared__ __align__(16) float g1sh[SPB][GPAD];
    __shared__ __align__(16) float h1sh[SPB][HPAD];
    __shared__ float wdsh[FD * 65];
    __shared__ float bdsh[FD];
    __shared__ float elem[SPB][FD];
    __shared__ int   lens[SPB];
    __shared__ int   ldec[SPB];

    const int tid = threadIdx.x;
    const int s0  = blockIdx.x * SPB;

    // ---- fill invalid output rows with -999 ----
    {
        const float4 m = make_float4(-999.f, -999.f, -999.f, -999.f);
        #pragma unroll
        for (int s = 0; s < SPB; s++) {
            int lc = lctx_g[s0 + s];
            float4* po = (float4*)(out + (size_t)(s0 + s) * TCC * FD);
            for (int i = lc * 2 + tid; i < (TCC * FD) / 4; i += NT) po[i] = m;
        }
    }
    // ---- zero B buffers ----
    {
        __half z = __float2half(0.f);
        __half* p0 = &uf0[0][0];
        for (int i = tid; i < 8 * U0S; i += NT) p0[i] = z;
        __half* p1 = &uf1[0][0];
        for (int i = tid; i < 8 * U1S; i += NT) p1[i] = z;
    }
    if (tid < SPB) { lens[tid] = lenx_g[s0 + tid]; ldec[tid] = lctx_g[s0 + tid] - 1; }
    for (int i = tid; i < FD * HID; i += NT) wdsh[(i >> 6) * 65 + (i & 63)] = Wd[i];
    if (tid < FD) bdsh[tid] = bd[tid];
    __syncthreads();

    const int w = tid >> 5, lane = tid & 31;
    const int g = lane >> 2, q = lane & 3;
    const int c0 = 2 * q;
    const int Tenc = max(max(lens[0], lens[1]), max(lens[2], lens[3]));
    const int Tdec = max(max(ldec[0], ldec[1]), max(ldec[2], ldec[3]));

    // ---- engine assignment: warps 0-15 layer0 tile w, 16-31 layer1 tile w-16 ----
    const bool isL0 = (w < 16);
    const int  tw   = isL0 ? w : (w - 16);
    const int  rA   = 16 * tw + g, rB = rA + 8;

    // A fragments (only the owning engine's array is populated; sized max 8)
    uint32_t fr[8][4];
    float ba, bb;
    if (isL0) {
        fr[0][0] = h2(Wih0[rA * INP + c0],     Wih0[rA * INP + c0 + 1]);
        fr[0][1] = h2(Wih0[rB * INP + c0],     Wih0[rB * INP + c0 + 1]);
        fr[0][2] = h2(Wih0[rA * INP + c0 + 8], Wih0[rA * INP + c0 + 9]);
        fr[0][3] = h2(Wih0[rB * INP + c0 + 8], Wih0[rB * INP + c0 + 9]);
        #pragma unroll
        for (int kt = 1; kt < 5; kt++) {
            int kb = (kt - 1) * 16;
            fr[kt][0] = h2(Whh0[rA * HID + kb + c0],     Whh0[rA * HID + kb + c0 + 1]);
            fr[kt][1] = h2(Whh0[rB * HID + kb + c0],     Whh0[rB * HID + kb + c0 + 1]);
            fr[kt][2] = h2(Whh0[rA * HID + kb + c0 + 8], Whh0[rA * HID + kb + c0 + 9]);
            fr[kt][3] = h2(Whh0[rB * HID + kb + c0 + 8], Whh0[rB * HID + kb + c0 + 9]);
        }
        ba = bih0[rA] + bhh0[rA]; bb = bih0[rB] + bhh0[rB];
    } else {
        #pragma unroll
        for (int kt = 0; kt < 4; kt++) {
            int kb = kt * 16;
            fr[kt][0] = h2(Wih1[rA * HID + kb + c0],     Wih1[rA * HID + kb + c0 + 1]);
            fr[kt][1] = h2(Wih1[rB * HID + kb + c0],     Wih1[rB * HID + kb + c0 + 1]);
            fr[kt][2] = h2(Wih1[rA * HID + kb + c0 + 8], Wih1[rA * HID + kb + c0 + 9]);
            fr[kt][3] = h2(Wih1[rB * HID + kb + c0 + 8], Wih1[rB * HID + kb + c0 + 9]);
        }
        #pragma unroll
        for (int kt = 4; kt < 8; kt++) {
            int kb = (kt - 4) * 16;
            fr[kt][0] = h2(Whh1[rA * HID + kb + c0],     Whh1[rA * HID + kb + c0 + 1]);
            fr[kt][1] = h2(Whh1[rB * HID + kb + c0],     Whh1[rB * HID + kb + c0 + 1]);
            fr[kt][2] = h2(Whh1[rA * HID + kb + c0 + 8], Whh1[rA * HID + kb + c0 + 9]);
            fr[kt][3] = h2(Whh1[rB * HID + kb + c0 + 8], Whh1[rB * HID + kb + c0 + 9]);
        }
        ba = bih1[rA] + bhh1[rA]; bb = bih1[rB] + bhh1[rB];
    }

    // ---- combine ownership: warps 0-7 layer0 units, warps 16-23 layer1 units ----
    const bool cb0 = (tid < 256);
    const bool cb1 = (tid >= 512 && tid < 768);
    const int  cu  = cb0 ? tid : (tid - 512);
    const int  cs  = (cu >> 6) & 3, cj = cu & 63;
    const int  myLe = lens[cs], myLd = ldec[cs];
    float cst = 0.f;

    const int ps = tid >> 4, pk = tid & 15;  // x prefetch (tid < 64)
    const int ds = tid >> 3, dk = tid & 7;   // ctx prefetch / projection (tid < 32)

    // gemm: one M-tile; engine selected by isL0. Chains split for shorter deps.
    auto gemm = [&]() {
        if (isL0) {
            float dA[4] = {ba, ba, bb, bb};
            float dB[4] = {0.f, 0.f, 0.f, 0.f};
            #pragma unroll
            for (int kt = 0; kt < 3; kt++) {
                uint32_t bv0 = *(const uint32_t*)&uf0[g][kt * 16 + c0];
                uint32_t bv1 = *(const uint32_t*)&uf0[g][kt * 16 + c0 + 8];
                mma16816(dA, fr[kt], bv0, bv1);
            }
            #pragma unroll
            for (int kt = 3; kt < 5; kt++) {
                uint32_t bv0 = *(const uint32_t*)&uf0[g][kt * 16 + c0];
                uint32_t bv1 = *(const uint32_t*)&uf0[g][kt * 16 + c0 + 8];
                mma16816(dB, fr[kt], bv0, bv1);
            }
            if (q < 2) {
                int sA = 2 * q, sB = 2 * q + 1;
                g0sh[sA][rA] = dA[0] + dB[0]; g0sh[sB][rA] = dA[1] + dB[1];
                g0sh[sA][rB] = dA[2] + dB[2]; g0sh[sB][rB] = dA[3] + dB[3];
            }
        } else {
            float eA[4] = {ba, ba, bb, bb};
            float eB[4] = {0.f, 0.f, 0.f, 0.f};
            #pragma unroll
            for (int kt = 0; kt < 4; kt++) {
                uint32_t bv0 = *(const uint32_t*)&uf1[g][kt * 16 + c0];
                uint32_t bv1 = *(const uint32_t*)&uf1[g][kt * 16 + c0 + 8];
                mma16816(eA, fr[kt], bv0, bv1);
            }
            #pragma unroll
            for (int kt = 4; kt < 8; kt++) {
                uint32_t bv0 = *(const uint32_t*)&uf1[g][kt * 16 + c0];
                uint32_t bv1 = *(const uint32_t*)&uf1[g][kt * 16 + c0 + 8];
                mma16816(eB, fr[kt], bv0, bv1);
            }
            if (q < 2) {
                int sA = 2 * q, sB = 2 * q + 1;
                g1sh[sA][rA] = eA[0] + eB[0]; g1sh[sB][rA] = eA[1] + eB[1];
                g1sh[sA][rB] = eA[2] + eB[2]; g1sh[sB][rB] = eA[3] + eB[3];
            }
        }
    };
    auto comb0 = [&]() {
        float fi = sigf(g0sh[cs][cj]);
        float ff = sigf(g0sh[cs][64 + cj]);
        float fg = tanha(g0sh[cs][128 + cj]);
        float fo = sigf(g0sh[cs][192 + cj]);
        cst = ff * cst + fi * fg;
        __half hf = __float2half(fo * tanha(cst));
        uf0[cs][16 + cj] = hf;
        uf1[cs][cj]      = hf;
    };
    auto comb1 = [&]() {
        float fi = sigf(g1sh[cs][cj]);
        float ff = sigf(g1sh[cs][64 + cj]);
        float fg = tanha(g1sh[cs][128 + cj]);
        float fo = sigf(g1sh[cs][192 + cj]);
        cst = ff * cst + fi * fg;
        float h = fo * tanha(cst);
        uf1[cs][64 + cj] = __float2half(h);
        h1sh[cs][cj] = h;
    };
    auto proj = [&](int row) {   // tid < 32 only
        float a0 = bdsh[dk], a1 = 0.f, a2 = 0.f, a3 = 0.f;
        #pragma unroll
        for (int j = 0; j < HID; j += 4) {
            a0 = fmaf(wdsh[dk * 65 + j    ], h1sh[ds][j    ], a0);
            a1 = fmaf(wdsh[dk * 65 + j + 1], h1sh[ds][j + 1], a1);
            a2 = fmaf(wdsh[dk * 65 + j + 2], h1sh[ds][j + 2], a2);
            a3 = fmaf(wdsh[dk * 65 + j + 3], h1sh[ds][j + 3], a3);
        }
        out[((size_t)(s0 + ds) * TCC + row) * FD + dk] = (a0 + a1) + (a2 + a3);
    };

    // ---- encoder prologue: x(0) -> uf0; g0(0) via L0 engine (h0 = 0) ----
    if (tid < 64) uf0[ps][pk] = __float2half(x[((size_t)(s0 + ps) * TW) * INP + pk]);
    __syncthreads();
    if (isL0) gemm();
    float xn = 0.f;
    if (tid < 64) xn = x[((size_t)(s0 + ps) * TW + min(1, TW - 1)) * INP + pk];
    __syncthreads();

    // ===================== encoder =====================
    for (int t = 0; t < Tenc; t++) {
        // phase A: combine + x rotate
        if (tid < 64) {
            uf0[ps][pk] = __float2half(xn);
            int tt = (t + 2 < TW) ? t + 2 : TW - 1;
            xn = x[((size_t)(s0 + ps) * TW + tt) * INP + pk];
        }
        if (cb0) { if (t < myLe) comb0(); }
        else if (cb1) { if (t > 0 && (t - 1) < myLe) comb1(); }
        __syncthreads();
        // phase B: both engines GEMM (g1(t), g0(t+1))
        gemm();
        __syncthreads();
    }
    // encoder epilogue: combine1(Tenc-1)
    if (cb1 && (Tenc - 1) < myLe) comb1();
    __syncthreads();

    // ===================== element = h1 @ Wd.T + bd =====================
    if (tid < 32) {
        float a0 = bdsh[dk], a1 = 0.f, a2 = 0.f, a3 = 0.f;
        #pragma unroll
        for (int j = 0; j < HID; j += 4) {
            a0 = fmaf(wdsh[dk * 65 + j    ], h1sh[ds][j    ], a0);
            a1 = fmaf(wdsh[dk * 65 + j + 1], h1sh[ds][j + 1], a1);
            a2 = fmaf(wdsh[dk * 65 + j + 2], h1sh[ds][j + 2], a2);
            a3 = fmaf(wdsh[dk * 65 + j + 3], h1sh[ds][j + 3], a3);
        }
        float e = (a0 + a1) + (a2 + a3);
        elem[ds][dk] = e;
        out[(size_t)(s0 + ds) * TCC * FD + dk] = e;   // row 0
    }
    __syncthreads();

    // ---- decoder prologue ----
    if (tid < 64 && pk < 8) uf0[ps][pk] = __float2half(elem[ps][pk]);
    if (tid < 32) uf0[ds][8 + dk] = __float2half(ctx[((size_t)(s0 + ds) * TCC) * FD + dk]);
    __syncthreads();
    if (isL0) gemm();
    float cn = 0.f;
    if (tid < 32) cn = ctx[((size_t)(s0 + ds) * TCC + min(1, TCC - 1)) * FD + dk];
    __syncthreads();

    // ===================== decoder =====================
    for (int t = 0; t < Tdec; t++) {
        // phase A: combine + ctx rotate
        if (tid < 32) {
            uf0[ds][8 + dk] = __float2half(cn);
            int tt = (t + 2 < TCC) ? t + 2 : TCC - 1;
            cn = ctx[((size_t)(s0 + ds) * TCC + tt) * FD + dk];
        }
        if (cb0) { if (t < myLd) comb0(); }
        else if (cb1) { if (t > 0 && (t - 1) < myLd) comb1(); }
        __syncthreads();
        // phase B: deferred projection + GEMMs
        if (tid < 32 && t > 0 && (t - 1) < ldec[ds]) proj(t);
        gemm();
        __syncthreads();
    }
    // decoder epilogue: combine1(Tdec-1), then final projection
    if (cb1 && (Tdec - 1) < myLd) comb1();
    __syncthreads();
    if (tid < 32 && (Tdec - 1) < ldec[ds]) proj(Tdec);
}

extern "C" void kernel_launch(void* const* d_in, const int* in_sizes, int n_in,
                              void* d_out, int out_size) {
    (void)in_sizes; (void)n_in; (void)out_size;
    lstm_ar_kernel<<<BB / SPB, NT>>>(
        (const float*)d_in[0],  (const int*)d_in[1],
        (const float*)d_in[2],  (const int*)d_in[3],
        (const float*)d_in[4],  (const float*)d_in[5],
        (const float*)d_in[6],  (const float*)d_in[7],
        (const float*)d_in[8],  (const float*)d_in[9],
        (const float*)d_in[10], (const float*)d_in[11],
        (const float*)d_in[12], (const float*)d_in[13],
        (float*)d_out);
}

// round 16
// speedup vs baseline: 1.9284x; 1.9284x over previous
#include <cuda_runtime.h>
#include <cuda_fp16.h>
#include <stdint.h>

#define BB   512
#define TW   512
#define TCC  512
#define INP  16
#define HID  64
#define FD   8
#define SPB  4
#define NT   512
#define HPAD 68
#define GTS  6     // transposed gate buffer stride (floats): STS.64-aligned, 2-way LDS conflict max
#define U0S  24    // uf0 stride in halfs (x only: 16 + pad)
#define U1S  136   // uf1 stride in halfs (h0|h1 = 128 + pad)

#define BAR() asm volatile("bar.sync 0;" ::: "memory")

__device__ __forceinline__ float tanha(float x) {
    float r; asm("tanh.approx.f32 %0, %1;" : "=f"(r) : "f"(x)); return r;
}
__device__ __forceinline__ float sigf(float x) {
    return fmaf(tanha(0.5f * x), 0.5f, 0.5f);
}
__device__ __forceinline__ uint32_t h2(float a, float b) {
    __half2 h = __floats2half2_rn(a, b);
    return *reinterpret_cast<uint32_t*>(&h);
}
__device__ __forceinline__ void mma16816(
    float* d, const uint32_t* a, uint32_t b0, uint32_t b1)
{
    asm("mma.sync.aligned.m16n8k16.row.col.f32.f16.f16.f32 "
        "{%0,%1,%2,%3},{%4,%5,%6,%7},{%8,%9},{%0,%1,%2,%3};"
        : "+f"(d[0]), "+f"(d[1]), "+f"(d[2]), "+f"(d[3])
        : "r"(a[0]), "r"(a[1]), "r"(a[2]), "r"(a[3]), "r"(b0), "r"(b1));
}

__global__ __launch_bounds__(NT, 1) void lstm_ar_kernel(
    const float* __restrict__ x,     const int* __restrict__ lenx_g,
    const float* __restrict__ ctx,   const int* __restrict__ lctx_g,
    const float* __restrict__ Wih0,  const float* __restrict__ Whh0,
    const float* __restrict__ bih0,  const float* __restrict__ bhh0,
    const float* __restrict__ Wih1,  const float* __restrict__ Whh1,
    const float* __restrict__ bih1,  const float* __restrict__ bhh1,
    const float* __restrict__ Wd,    const float* __restrict__ bd,
    float* __restrict__ out)
{
    __shared__ __align__(16) __half uf0[8][U0S];     // x / dec-input per sample
    __shared__ __align__(16) __half uf1[8][U1S];     // [h0|h1] per sample
    __shared__ __align__(16) float g0t[4 * HID][GTS]; // gates L0, transposed [row][sample]
    __shared__ __align__(16) float g1t[4 * HID][GTS]; // gates L1, transposed
    __shared__ __align__(16) float h1sh[SPB][HPAD];
    __shared__ float wdsh[FD * 65];
    __shared__ float bdsh[FD];
    __shared__ float elem[SPB][FD];
    __shared__ int   lens[SPB];
    __shared__ int   ldec[SPB];

    const int tid = threadIdx.x;
    const int s0  = blockIdx.x * SPB;

    // ---- fill invalid output rows with -999 ----
    {
        const float4 m = make_float4(-999.f, -999.f, -999.f, -999.f);
        #pragma unroll
        for (int s = 0; s < SPB; s++) {
            int lc = lctx_g[s0 + s];
            float4* po = (float4*)(out + (size_t)(s0 + s) * TCC * FD);
            for (int i = lc * 2 + tid; i < (TCC * FD) / 4; i += NT) po[i] = m;
        }
    }
    // ---- zero activation buffers (h0 = h1 = 0; samples 4..7 stay zero) ----
    {
        __half z = __float2half(0.f);
        __half* p0 = &uf0[0][0];
        for (int i = tid; i < 8 * U0S; i += NT) p0[i] = z;
        __half* p1 = &uf1[0][0];
        for (int i = tid; i < 8 * U1S; i += NT) p1[i] = z;
        float* pg = &g0t[0][0];
        for (int i = tid; i < 4 * HID * GTS; i += NT) pg[i] = 0.f;
        float* ph = &g1t[0][0];
        for (int i = tid; i < 4 * HID * GTS; i += NT) ph[i] = 0.f;
    }
    if (tid < SPB) { lens[tid] = lenx_g[s0 + tid]; ldec[tid] = lctx_g[s0 + tid] - 1; }
    for (int i = tid; i < FD * HID; i += NT) wdsh[(i >> 6) * 65 + (i & 63)] = Wd[i];
    if (tid < FD) bdsh[tid] = bd[tid];
    __syncthreads();

    const int w = tid >> 5, lane = tid & 31;
    const int g = lane >> 2, q = lane & 3;
    const int c0 = 2 * q;
    const int Tenc = max(max(lens[0], lens[1]), max(lens[2], lens[3]));
    const int Tdec = max(max(ldec[0], ldec[1]), max(ldec[2], ldec[3]));

    if (w < 8) {
        // ================= LAYER-0 ENGINE (warps 0-7) =================
        const int rA0 = 32 * w + g,      rB0 = rA0 + 8;
        const int rA1 = 32 * w + 16 + g, rB1 = rA1 + 8;
        uint32_t f0[2][5][4];
        float b0A[2], b0B[2];
        #pragma unroll
        for (int j = 0; j < 2; j++) {
            int rA = j ? rA1 : rA0, rB = j ? rB1 : rB0;
            f0[j][0][0] = h2(Wih0[rA * INP + c0],     Wih0[rA * INP + c0 + 1]);
            f0[j][0][1] = h2(Wih0[rB * INP + c0],     Wih0[rB * INP + c0 + 1]);
            f0[j][0][2] = h2(Wih0[rA * INP + c0 + 8], Wih0[rA * INP + c0 + 9]);
            f0[j][0][3] = h2(Wih0[rB * INP + c0 + 8], Wih0[rB * INP + c0 + 9]);
            #pragma unroll
            for (int kt = 1; kt < 5; kt++) {
                int kb = (kt - 1) * 16;
                f0[j][kt][0] = h2(Whh0[rA * HID + kb + c0],     Whh0[rA * HID + kb + c0 + 1]);
                f0[j][kt][1] = h2(Whh0[rB * HID + kb + c0],     Whh0[rB * HID + kb + c0 + 1]);
                f0[j][kt][2] = h2(Whh0[rA * HID + kb + c0 + 8], Whh0[rA * HID + kb + c0 + 9]);
                f0[j][kt][3] = h2(Whh0[rB * HID + kb + c0 + 8], Whh0[rB * HID + kb + c0 + 9]);
            }
            b0A[j] = bih0[rA] + bhh0[rA]; b0B[j] = bih0[rB] + bhh0[rB];
        }
        const int cs = tid >> 6, cj = tid & 63;
        const int myLe = lens[cs], myLd = ldec[cs];
        const int ps = tid >> 4, pk = tid & 15;  // tid < 64
        const int ds = tid >> 3, dk = tid & 7;   // tid < 32
        float cst = 0.f;

        // gemm0: g0 = [x|h0] GEMM. kt=0 reads x from uf0; kt 1-4 read h0 from uf1.
        auto gemm0 = [&]() {
            float dA0[4] = {b0A[0], b0A[0], b0B[0], b0B[0]};
            float dA1[4] = {b0A[1], b0A[1], b0B[1], b0B[1]};
            float dB0[4] = {0.f, 0.f, 0.f, 0.f};
            float dB1[4] = {0.f, 0.f, 0.f, 0.f};
            {
                uint32_t bv0 = *(const uint32_t*)&uf0[g][c0];
                uint32_t bv1 = *(const uint32_t*)&uf0[g][c0 + 8];
                mma16816(dA0, f0[0][0], bv0, bv1);
                mma16816(dA1, f0[1][0], bv0, bv1);
            }
            #pragma unroll
            for (int kt = 1; kt < 3; kt++) {
                uint32_t bv0 = *(const uint32_t*)&uf1[g][(kt - 1) * 16 + c0];
                uint32_t bv1 = *(const uint32_t*)&uf1[g][(kt - 1) * 16 + c0 + 8];
                mma16816(dA0, f0[0][kt], bv0, bv1);
                mma16816(dA1, f0[1][kt], bv0, bv1);
            }
            #pragma unroll
            for (int kt = 3; kt < 5; kt++) {
                uint32_t bv0 = *(const uint32_t*)&uf1[g][(kt - 1) * 16 + c0];
                uint32_t bv1 = *(const uint32_t*)&uf1[g][(kt - 1) * 16 + c0 + 8];
                mma16816(dB0, f0[0][kt], bv0, bv1);
                mma16816(dB1, f0[1][kt], bv0, bv1);
            }
            if (q < 2) {   // transposed stores: 4x STS.64
                *(float2*)&g0t[rA0][c0] = make_float2(dA0[0] + dB0[0], dA0[1] + dB0[1]);
                *(float2*)&g0t[rB0][c0] = make_float2(dA0[2] + dB0[2], dA0[3] + dB0[3]);
                *(float2*)&g0t[rA1][c0] = make_float2(dA1[0] + dB1[0], dA1[1] + dB1[1]);
                *(float2*)&g0t[rB1][c0] = make_float2(dA1[2] + dB1[2], dA1[3] + dB1[3]);
            }
        };
        auto comb0 = [&]() {
            float fi = sigf(g0t[cj][cs]);
            float ff = sigf(g0t[64 + cj][cs]);
            float fg = tanha(g0t[128 + cj][cs]);
            float fo = sigf(g0t[192 + cj][cs]);
            cst = ff * cst + fi * fg;
            uf1[cs][cj] = __float2half(fo * tanha(cst));   // single h0 store
        };
        auto proj = [&](int row) {   // tid < 32 only
            float a0 = bdsh[dk], a1 = 0.f, a2 = 0.f, a3 = 0.f;
            #pragma unroll
            for (int j = 0; j < HID; j += 4) {
                a0 = fmaf(wdsh[dk * 65 + j    ], h1sh[ds][j    ], a0);
                a1 = fmaf(wdsh[dk * 65 + j + 1], h1sh[ds][j + 1], a1);
                a2 = fmaf(wdsh[dk * 65 + j + 2], h1sh[ds][j + 2], a2);
                a3 = fmaf(wdsh[dk * 65 + j + 3], h1sh[ds][j + 3], a3);
            }
            out[((size_t)(s0 + ds) * TCC + row) * FD + dk] = (a0 + a1) + (a2 + a3);
        };

        // ---- encoder prologue ----
        if (tid < 64) uf0[ps][pk] = __float2half(x[((size_t)(s0 + ps) * TW) * INP + pk]);
        BAR();                                   // bar 1
        gemm0();                                 // g0(0), h0 = 0
        float xn = 0.f;
        if (tid < 64) xn = x[((size_t)(s0 + ps) * TW + min(1, TW - 1)) * INP + pk];
        BAR();                                   // bar 2
        // ---- encoder ----
        for (int t = 0; t < Tenc; t++) {
            if (tid < 64) {
                uf0[ps][pk] = __float2half(xn);
                int tt = (t + 2 < TW) ? t + 2 : TW - 1;
                xn = x[((size_t)(s0 + ps) * TW + tt) * INP + pk];
            }
            if (t < myLe) comb0();
            BAR();                               // loop bar a
            gemm0();                             // g0(t+1)
            BAR();                               // loop bar b
        }
        BAR();                                   // bar: L1 combine1(Tenc-1)
        // ---- element = h1 @ Wd.T + bd ----
        if (tid < 32) {
            float a0 = bdsh[dk], a1 = 0.f, a2 = 0.f, a3 = 0.f;
            #pragma unroll
            for (int j = 0; j < HID; j += 4) {
                a0 = fmaf(wdsh[dk * 65 + j    ], h1sh[ds][j    ], a0);
                a1 = fmaf(wdsh[dk * 65 + j + 1], h1sh[ds][j + 1], a1);
                a2 = fmaf(wdsh[dk * 65 + j + 2], h1sh[ds][j + 2], a2);
                a3 = fmaf(wdsh[dk * 65 + j + 3], h1sh[ds][j + 3], a3);
            }
            float e = (a0 + a1) + (a2 + a3);
            elem[ds][dk] = e;
            out[(size_t)(s0 + ds) * TCC * FD + dk] = e;   // row 0
        }
        BAR();                                   // bar: elem ready
        // ---- decoder prologue ----
        if (tid < 64 && pk < 8) uf0[ps][pk] = __float2half(elem[ps][pk]);
        if (tid < 32) uf0[ds][8 + dk] = __float2half(ctx[((size_t)(s0 + ds) * TCC) * FD + dk]);
        BAR();                                   // bar: dec input ready
        gemm0();                                 // g0_dec(0)
        float cn = 0.f;
        if (tid < 32) cn = ctx[((size_t)(s0 + ds) * TCC + min(1, TCC - 1)) * FD + dk];
        BAR();                                   // bar
        // ---- decoder ----
        for (int t = 0; t < Tdec; t++) {
            if (tid < 32) {
                uf0[ds][8 + dk] = __float2half(cn);
                int tt = (t + 2 < TCC) ? t + 2 : TCC - 1;
                cn = ctx[((size_t)(s0 + ds) * TCC + tt) * FD + dk];
            }
            if (t < myLd) comb0();
            BAR();                               // loop bar a
            gemm0();                             // g0(t+1)
            if (tid < 32 && t > 0 && (t - 1) < ldec[ds]) proj(t);   // drain window
            BAR();                               // loop bar b
        }
        BAR();                                   // bar: L1 combine1(Tdec-1)
        if (tid < 32 && (Tdec - 1) < ldec[ds]) proj(Tdec);
    } else {
        // ================= LAYER-1 ENGINE (warps 8-15) =================
        const int wj  = w - 8;
        const int rA0 = 32 * wj + g,      rB0 = rA0 + 8;
        const int rA1 = 32 * wj + 16 + g, rB1 = rA1 + 8;
        uint32_t f1[2][8][4];
        float b1A[2], b1B[2];
        #pragma unroll
        for (int j = 0; j < 2; j++) {
            int rA = j ? rA1 : rA0, rB = j ? rB1 : rB0;
            #pragma unroll
            for (int kt = 0; kt < 4; kt++) {
                int kb = kt * 16;
                f1[j][kt][0] = h2(Wih1[rA * HID + kb + c0],     Wih1[rA * HID + kb + c0 + 1]);
                f1[j][kt][1] = h2(Wih1[rB * HID + kb + c0],     Wih1[rB * HID + kb + c0 + 1]);
                f1[j][kt][2] = h2(Wih1[rA * HID + kb + c0 + 8], Wih1[rA * HID + kb + c0 + 9]);
                f1[j][kt][3] = h2(Wih1[rB * HID + kb + c0 + 8], Wih1[rB * HID + kb + c0 + 9]);
            }
            #pragma unroll
            for (int kt = 4; kt < 8; kt++) {
                int kb = (kt - 4) * 16;
                f1[j][kt][0] = h2(Whh1[rA * HID + kb + c0],     Whh1[rA * HID + kb + c0 + 1]);
                f1[j][kt][1] = h2(Whh1[rB * HID + kb + c0],     Whh1[rB * HID + kb + c0 + 1]);
                f1[j][kt][2] = h2(Whh1[rA * HID + kb + c0 + 8], Whh1[rA * HID + kb + c0 + 9]);
                f1[j][kt][3] = h2(Whh1[rB * HID + kb + c0 + 8], Whh1[rB * HID + kb + c0 + 9]);
            }
            b1A[j] = bih1[rA] + bhh1[rA]; b1B[j] = bih1[rB] + bhh1[rB];
        }
        const int cu = tid - 256;
        const int cs = cu >> 6, cj = cu & 63;
        const int myLe = lens[cs], myLd = ldec[cs];
        float cst = 0.f;

        auto gemm1 = [&]() {
            float eA0[4] = {b1A[0], b1A[0], b1B[0], b1B[0]};
            float eA1[4] = {b1A[1], b1A[1], b1B[1], b1B[1]};
            float eB0[4] = {0.f, 0.f, 0.f, 0.f};
            float eB1[4] = {0.f, 0.f, 0.f, 0.f};
            #pragma unroll
            for (int kt = 0; kt < 4; kt++) {
                uint32_t bv0 = *(const uint32_t*)&uf1[g][kt * 16 + c0];
                uint32_t bv1 = *(const uint32_t*)&uf1[g][kt * 16 + c0 + 8];
                mma16816(eA0, f1[0][kt], bv0, bv1);
                mma16816(eA1, f1[1][kt], bv0, bv1);
            }
            #pragma unroll
            for (int kt = 4; kt < 8; kt++) {
                uint32_t bv0 = *(const uint32_t*)&uf1[g][kt * 16 + c0];
                uint32_t bv1 = *(const uint32_t*)&uf1[g][kt * 16 + c0 + 8];
                mma16816(eB0, f1[0][kt], bv0, bv1);
                mma16816(eB1, f1[1][kt], bv0, bv1);
            }
            if (q < 2) {   // transposed stores: 4x STS.64
                *(float2*)&g1t[rA0][c0] = make_float2(eA0[0] + eB0[0], eA0[1] + eB0[1]);
                *(float2*)&g1t[rB0][c0] = make_float2(eA0[2] + eB0[2], eA0[3] + eB0[3]);
                *(float2*)&g1t[rA1][c0] = make_float2(eA1[0] + eB1[0], eA1[1] + eB1[1]);
                *(float2*)&g1t[rB1][c0] = make_float2(eA1[2] + eB1[2], eA1[3] + eB1[3]);
            }
        };
        auto comb1 = [&]() {
            float fi = sigf(g1t[cj][cs]);
            float ff = sigf(g1t[64 + cj][cs]);
            float fg = tanha(g1t[128 + cj][cs]);
            float fo = sigf(g1t[192 + cj][cs]);
            cst = ff * cst + fi * fg;
            float h = fo * tanha(cst);
            uf1[cs][64 + cj] = __float2half(h);
            h1sh[cs][cj] = h;
        };

        // ---- encoder prologue (mirror bars) ----
        BAR();                                   // bar 1
        BAR();                                   // bar 2
        // ---- encoder ----
        for (int t = 0; t < Tenc; t++) {
            if (t > 0 && (t - 1) < myLe) comb1();
            BAR();                               // loop bar a
            gemm1();                             // g1(t)
            BAR();                               // loop bar b
        }
        if ((Tenc - 1) < myLe) comb1();
        BAR();                                   // bar: h1 final ready
        BAR();                                   // bar: elem
        BAR();                                   // bar: dec input
        BAR();                                   // bar: g0_dec(0)
        // ---- decoder ----
        for (int t = 0; t < Tdec; t++) {
            if (t > 0 && (t - 1) < myLd) comb1();
            BAR();                               // loop bar a
            gemm1();                             // g1(t)
            BAR();                               // loop bar b
        }
        if ((Tdec - 1) < myLd) comb1();
        BAR();                                   // bar: h1(Tdec-1) ready
    }
}

extern "C" void kernel_launch(void* const* d_in, const int* in_sizes, int n_in,
                              void* d_out, int out_size) {
    (void)in_sizes; (void)n_in; (void)out_size;
    lstm_ar_kernel<<<BB / SPB, NT>>>(
        (const float*)d_in[0],  (const int*)d_in[1],
        (const float*)d_in[2],  (const int*)d_in[3],
        (const float*)d_in[4],  (const float*)d_in[5],
        (const float*)d_in[6],  (const float*)d_in[7],
        (const float*)d_in[8],  (const float*)d_in[9],
        (const float*)d_in[10], (const float*)d_in[11],
        (const float*)d_in[12], (const float*)d_in[13],
        (float*)d_out);
}